// round 12
// baseline (speedup 1.0000x reference)
#include <cuda_runtime.h>
#include <math.h>
#include <float.h>

#define NMAX      26400
#define KTOP      1000
#define CONF      0.001f
#define NMS_THR   0.6f
#define CAP       2048
#define BS        512
#define MW        13          // mask words per row (covers V <= 416)
#define VMAXF     408         // fast-path limit
#define NCLS      128

// ---------------- scratch (no allocation allowed) ----------------
__device__ float4  g_boxes4[NMAX];
__device__ float2  g_pack[NMAX];             // {score, bitcast(cls)}
__device__ int     g_ccnt[NCLS];             // starts zeroed; reset each run
__device__ float2  g_clist[NCLS * CAP];      // {score, bitcast(anchor idx)}

// ---------------- kernel 1: decode, one warp per anchor ----------------
__global__ void __launch_bounds__(256) decode_kernel(
    const float* __restrict__ reg, const float* __restrict__ obj,
    const float* __restrict__ cls, const float* __restrict__ grid,
    const float* __restrict__ anch, const float* __restrict__ strd,
    int N, int C)
{
    int warp = (blockIdx.x * blockDim.x + threadIdx.x) >> 5;
    int lane = threadIdx.x & 31;
    if (warp >= N) return;

    float vmax = -FLT_MAX; int amax = 0x7fffffff;
    float v0 = 0.f, v1 = 0.f, v2 = 0.f, v3 = 0.f;
    int nq = (C + 3) >> 2;
    bool has = lane < nq;
    if (has) {
        const float4* cl4 = (const float4*)(cls + (size_t)warp * C);
        float4 q = cl4[lane];
        v0 = q.x; v1 = q.y; v2 = q.z; v3 = q.w;
        int base = lane << 2;
        vmax = v0; amax = base;
        if (v1 > vmax) { vmax = v1; amax = base + 1; }
        if (v2 > vmax) { vmax = v2; amax = base + 2; }
        if (v3 > vmax) { vmax = v3; amax = base + 3; }
    }
    for (int off = 16; off; off >>= 1) {
        float ov = __shfl_down_sync(0xffffffffu, vmax, off);
        int   oa = __shfl_down_sync(0xffffffffu, amax, off);
        if (ov > vmax || (ov == vmax && oa < amax)) { vmax = ov; amax = oa; }
    }
    vmax = __shfl_sync(0xffffffffu, vmax, 0);
    amax = __shfl_sync(0xffffffffu, amax, 0);

    float se = 0.f;
    if (has) {
        se = expf(v0 - vmax) + expf(v1 - vmax)
           + expf(v2 - vmax) + expf(v3 - vmax);
    }
    for (int off = 16; off; off >>= 1)
        se += __shfl_down_sync(0xffffffffu, se, off);

    if (lane == 0) {
        float sig_obj = 1.f / (1.f + expf(-obj[warp]));
        float score   = sig_obj * (1.f / se);
        g_pack[warp] = make_float2(score, __int_as_float(amax));

        if (score >= CONF) {
            int slot = atomicAdd(&g_ccnt[amax], 1);
            if (slot < CAP)
                g_clist[amax * CAP + slot] = make_float2(score, __int_as_float(warp));
        }

        float s  = strd[warp];
        float gx = grid[warp * 2 + 0], gy = grid[warp * 2 + 1];
        float aw = anch[warp * 2 + 0], ah = anch[warp * 2 + 1];
        float4 r = ((const float4*)reg)[warp];

        float cx = (1.f / (1.f + expf(-r.x)) + gx) * s;
        float cy = (1.f / (1.f + expf(-r.y)) + gy) * s;
        float w  = expf(r.z) * aw;
        float h  = expf(r.w) * ah;

        float4 b;
        b.x = fminf(fmaxf((cx - 0.5f * w) / 640.0f, 0.f), 1.f);
        b.y = fminf(fmaxf((cy - 0.5f * h) / 640.0f, 0.f), 1.f);
        b.z = fminf(fmaxf((cx + 0.5f * w) / 640.0f, 0.f), 1.f);
        b.w = fminf(fmaxf((cy + 0.5f * h) / 640.0f, 0.f), 1.f);
        g_boxes4[warp] = b;
    }
}

// ---------------- kernel 2: fused per-class sort+fill+gather+mask+resolve ----------------
__global__ void __launch_bounds__(BS) nms_kernel(
    float* __restrict__ out_boxes, float* __restrict__ out_scores,
    float* __restrict__ out_keep, int N)
{
    __shared__ float    sc[CAP];
    __shared__ int      sidx[CAP];
    __shared__ float    bx1[VMAXF], by1[VMAXF], bx2[VMAXF], by2[VMAXF], sar[VMAXF];
    __shared__ unsigned smask[VMAXF * MW];
    __shared__ unsigned s_flag[16], aliveW[16];
    __shared__ int      s_run, s_wsum[BS / 32];

    const int cls  = blockIdx.x;
    const int tid  = threadIdx.x;
    const int wid  = tid >> 5;
    const int lane = tid & 31;

    if (tid == 0) s_run = 0;
    if (tid < 16) s_flag[tid] = 0u;

    // ---- Phase A: read pre-binned candidate list ----
    int cnt = min(g_ccnt[cls], CAP);
    for (int q = tid; q < cnt; q += BS) {
        float2 p = g_clist[cls * CAP + q];
        sc[q]   = p.x;
        sidx[q] = __float_as_int(p.y);
    }
    if (tid == 0) g_ccnt[cls] = 0;   // reset for next graph replay

    // ---- Phase B: bitonic sort (score desc, idx asc) ----
    int M = 2; while (M < cnt) M <<= 1;
    for (int i = cnt + tid; i < M; i += BS) { sc[i] = -FLT_MAX; sidx[i] = 0x7fffffff; }
    __syncthreads();

    if (M >= 32 && M <= BS) {
        for (int k = 2; k <= M; k <<= 1) {
            int j = k >> 1;
            for (; j >= 32; j >>= 1) {
                if (tid < M) {
                    int i = tid, l = i ^ j;
                    if (l > i) {
                        float si = sc[i], sl = sc[l];
                        int   ii = sidx[i], il = sidx[l];
                        bool lPrec = (sl > si) || (sl == si && il < ii);
                        if (lPrec == ((i & k) == 0)) {
                            sc[i] = sl; sc[l] = si;
                            sidx[i] = il; sidx[l] = ii;
                        }
                    }
                }
                __syncthreads();
            }
            if (tid < M) {
                for (; j > 0; j >>= 1) {
                    int i = tid, l = i ^ j;
                    if (l > i) {
                        float si = sc[i], sl = sc[l];
                        int   ii = sidx[i], il = sidx[l];
                        bool lPrec = (sl > si) || (sl == si && il < ii);
                        if (lPrec == ((i & k) == 0)) {
                            sc[i] = sl; sc[l] = si;
                            sidx[i] = il; sidx[l] = ii;
                        }
                    }
                    __syncwarp();
                }
            }
            __syncthreads();
        }
    } else {
        for (int k = 2; k <= M; k <<= 1) {
            for (int j = k >> 1; j > 0; j >>= 1) {
                for (int i = tid; i < M; i += BS) {
                    int l = i ^ j;
                    if (l > i) {
                        float si = sc[i], sl = sc[l];
                        int   ii = sidx[i], il = sidx[l];
                        bool lPrec = (sl > si) || (sl == si && il < ii);
                        if (lPrec == ((i & k) == 0)) {
                            sc[i] = sl; sc[l] = si;
                            sidx[i] = il; sidx[l] = ii;
                        }
                    }
                }
                __syncthreads();
            }
        }
    }

    // ---- Phase C: fill remaining slots with lowest-index non-candidates ----
    const int V = min(cnt, KTOP);
    const int need = KTOP - V;
    if (need > 0) {
        for (int base = 0;; base += BS) {
            int a = base + tid;
            int flag = 0;
            if (a < N) {
                float2 p = g_pack[a];
                flag = !(__float_as_int(p.y) == cls && p.x >= CONF);
            }
            unsigned m = __ballot_sync(0xffffffffu, flag);
            int wpos = __popc(m & ((1u << lane) - 1u));
            if (lane == 0) s_wsum[wid] = __popc(m);
            __syncthreads();
            int off = 0, tot = 0;
            #pragma unroll
            for (int w = 0; w < BS / 32; w++) {
                if (w < wid) off += s_wsum[w];
                tot += s_wsum[w];
            }
            int run = s_run;
            int pos = run + off + wpos;
            if (flag && pos < need && V + pos < CAP) { sc[V + pos] = -1.0f; sidx[V + pos] = a; }
            __syncthreads();
            if (tid == 0) s_run = run + tot;
            __syncthreads();
            if (run + tot >= need) break;
            if (base + BS >= N) break;
        }
    }
    __syncthreads();

    const bool fast = (V <= VMAXF);

    // ---- Phase D: gather boxes -> out_boxes; stage first V ----
    for (int k = tid; k < KTOP; k += BS) {
        int a = sidx[k];
        float4 b = g_boxes4[a];
        if (fast && k < V) {
            bx1[k] = b.x; by1[k] = b.y; bx2[k] = b.z; by2[k] = b.w;
            sar[k] = (b.z - b.x) * (b.w - b.y);
        }
        ((float4*)out_boxes)[(size_t)cls * KTOP + k] = b;
    }
    __syncthreads();

    if (fast) {
        // ---- Phase E: warp-cooperative tiled IoU mask build (smem) ----
        const int nt = (V + 31) >> 5;
        const int T  = nt * (nt + 1) / 2;
        for (int t = wid; t < T; t += BS / 32) {
            int ti = 0, rem = t;
            while (rem >= nt - ti) { rem -= nt - ti; ti++; }
            int tj = ti + rem;

            int j = (tj << 5) + lane;
            bool vj = j < V;
            float xj1 = 0.f, yj1 = 0.f, xj2 = 0.f, yj2 = 0.f, aj = 0.f;
            if (vj) { xj1 = bx1[j]; yj1 = by1[j]; xj2 = bx2[j]; yj2 = by2[j]; aj = sar[j]; }

            int imax = min(32, V - (ti << 5));
            for (int r = 0; r < imax; r++) {
                int i = (ti << 5) + r;
                float xi1 = bx1[i], yi1 = by1[i], xi2 = bx2[i], yi2 = by2[i];
                float ai  = sar[i];
                float xx1 = fmaxf(xi1, xj1);
                float yy1 = fmaxf(yi1, yj1);
                float xx2 = fminf(xi2, xj2);
                float yy2 = fminf(yi2, yj2);
                float ww = fmaxf(1e-28f, xx2 - xx1);
                float hh = fmaxf(1e-28f, yy2 - yy1);
                float inter = ww * hh;
                float iou = inter / (ai + aj - inter + 1e-14f);
                bool bit = vj && (j > i) && (iou > NMS_THR);
                unsigned word = __ballot_sync(0xffffffffu, bit);
                if (lane == 0) {
                    smask[i * MW + tj] = word;   // all upper-tri words written
                    if (word) atomicOr(&s_flag[i >> 5], 1u << (i & 31));
                }
            }
        }
        __syncthreads();

        // ---- resolve: single thread, alive bitset in registers ----
        if (tid == 0) {
            unsigned alive[MW], flg[MW];
            #pragma unroll
            for (int w = 0; w < MW; w++) {
                int lo = w << 5;
                unsigned a = 0;
                if (lo + 32 <= V)      a = 0xffffffffu;
                else if (lo < V)       a = (1u << (V - lo)) - 1u;
                alive[w] = a;
                flg[w]   = s_flag[w];
            }
            #pragma unroll
            for (int w0 = 0; w0 < MW; w0++) {
                if ((w0 << 5) >= V) break;
                unsigned done = 0;
                while (true) {
                    unsigned aw = alive[w0] & ~done;
                    if (!aw) break;
                    unsigned actw = aw & flg[w0];
                    if (!actw) break;              // rest of word suppresses nothing
                    int b = __ffs(actw) - 1;
                    int i = (w0 << 5) + b;
                    done |= (aw & ((1u << b) - 1u)) | (1u << b);
                    const unsigned* row = &smask[i * MW];
                    #pragma unroll
                    for (int w = 0; w < MW; w++)
                        if (w >= w0) alive[w] &= ~row[w];   // compile-time guard
                }
            }
            #pragma unroll
            for (int w = 0; w < MW; w++) aliveW[w] = alive[w];
            for (int w = MW; w < 16; w++) aliveW[w] = 0u;
        }
        __syncthreads();

        // ---- Phase F: outputs ----
        for (int k = tid; k < KTOP; k += BS) {
            float kp = 0.f;
            if (k < V) kp = ((aliveW[k >> 5] >> (k & 31)) & 1u) ? 1.f : 0.f;
            out_scores[(size_t)cls * KTOP + k] = sc[k] * kp;
            out_keep[(size_t)cls * KTOP + k]   = kp;
        }
    } else {
        // ---- fallback (V > VMAXF): barriered greedy NMS ----
        int* kfb = (int*)smask;
        for (int k = tid; k < V; k += BS) kfb[k] = 1;
        __syncthreads();
        for (int i = 0; i < V; i++) {
            if (kfb[i]) {
                float4 bi = g_boxes4[sidx[i]];
                float ai = (bi.z - bi.x) * (bi.w - bi.y);
                for (int j = i + 1 + tid; j < V; j += BS) {
                    if (kfb[j]) {
                        float4 bj = g_boxes4[sidx[j]];
                        float aj = (bj.z - bj.x) * (bj.w - bj.y);
                        float xx1 = fmaxf(bi.x, bj.x);
                        float yy1 = fmaxf(bi.y, bj.y);
                        float xx2 = fminf(bi.z, bj.z);
                        float yy2 = fminf(bi.w, bj.w);
                        float ww = fmaxf(1e-28f, xx2 - xx1);
                        float hh = fmaxf(1e-28f, yy2 - yy1);
                        float inter = ww * hh;
                        float iou = inter / (ai + aj - inter + 1e-14f);
                        if (iou > NMS_THR) kfb[j] = 0;
                    }
                }
            }
            __syncthreads();
        }
        for (int k = tid; k < KTOP; k += BS) {
            float kp = (k < V && kfb[k]) ? 1.f : 0.f;
            out_scores[(size_t)cls * KTOP + k] = sc[k] * kp;
            out_keep[(size_t)cls * KTOP + k]   = kp;
        }
    }
}

// ---------------- launch ----------------
extern "C" void kernel_launch(void* const* d_in, const int* in_sizes, int n_in,
                              void* d_out, int out_size)
{
    const float* reg  = (const float*)d_in[0];
    const float* obj  = (const float*)d_in[1];
    const float* cls  = (const float*)d_in[2];
    const float* grid = (const float*)d_in[3];
    const float* anch = (const float*)d_in[4];
    const float* strd = (const float*)d_in[5];

    int N = in_sizes[0] / 4;
    int C = in_sizes[2] / N;

    float* out = (float*)d_out;
    float* out_boxes  = out;                         // [C, K, 4]
    float* out_scores = out + (size_t)C * KTOP * 4;  // [C, K]
    float* out_keep   = out + (size_t)C * KTOP * 5;  // [C, K]

    int blocks = (N + 7) / 8;
    decode_kernel<<<blocks, 256>>>(reg, obj, cls, grid, anch, strd, N, C);
    nms_kernel<<<C, BS>>>(out_boxes, out_scores, out_keep, N);
}

// round 13
// speedup vs baseline: 1.3112x; 1.3112x over previous
#include <cuda_runtime.h>
#include <math.h>
#include <float.h>

#define NMAX      26400
#define KTOP      1000
#define CONF      0.001f
#define NMS_THR   0.6f
#define CAP       2048
#define BS        512
#define MW        13          // mask words per row (covers V <= 416)
#define VMAXF     408         // fast-path limit
#define NCLS      128
#define MSPLIT    4           // mask kernel tile splits

// ---------------- scratch (no allocation allowed) ----------------
__device__ float4  g_boxes4[NMAX];
__device__ float2  g_pack[NMAX];             // {score, bitcast(cls)}
__device__ int     g_ccnt[NCLS];             // starts zeroed; reset each run
__device__ float2  g_clist[NCLS * CAP];      // {score, bitcast(anchor idx)}
__device__ float   g_ssc[NCLS * KTOP];       // sorted scores (incl. -1 fills)
__device__ int     g_sidx[NCLS * KTOP];      // sorted anchor indices
__device__ float4  g_sbox[NCLS * VMAXF];     // staged boxes (k < V)
__device__ float   g_sarA[NCLS * VMAXF];     // staged areas
__device__ int     g_V[NCLS];
__device__ unsigned g_mask[NCLS * VMAXF * MW];
__device__ unsigned g_flag[NCLS * 16];

// ---------------- kernel 1: decode, one warp per anchor ----------------
__global__ void __launch_bounds__(256) decode_kernel(
    const float* __restrict__ reg, const float* __restrict__ obj,
    const float* __restrict__ cls, const float* __restrict__ grid,
    const float* __restrict__ anch, const float* __restrict__ strd,
    int N, int C)
{
    int warp = (blockIdx.x * blockDim.x + threadIdx.x) >> 5;
    int lane = threadIdx.x & 31;
    if (warp >= N) return;

    float vmax = -FLT_MAX; int amax = 0x7fffffff;
    float v0 = 0.f, v1 = 0.f, v2 = 0.f, v3 = 0.f;
    int nq = (C + 3) >> 2;
    bool has = lane < nq;
    if (has) {
        const float4* cl4 = (const float4*)(cls + (size_t)warp * C);
        float4 q = cl4[lane];
        v0 = q.x; v1 = q.y; v2 = q.z; v3 = q.w;
        int base = lane << 2;
        vmax = v0; amax = base;
        if (v1 > vmax) { vmax = v1; amax = base + 1; }
        if (v2 > vmax) { vmax = v2; amax = base + 2; }
        if (v3 > vmax) { vmax = v3; amax = base + 3; }
    }
    for (int off = 16; off; off >>= 1) {
        float ov = __shfl_down_sync(0xffffffffu, vmax, off);
        int   oa = __shfl_down_sync(0xffffffffu, amax, off);
        if (ov > vmax || (ov == vmax && oa < amax)) { vmax = ov; amax = oa; }
    }
    vmax = __shfl_sync(0xffffffffu, vmax, 0);
    amax = __shfl_sync(0xffffffffu, amax, 0);

    float se = 0.f;
    if (has) {
        se = expf(v0 - vmax) + expf(v1 - vmax)
           + expf(v2 - vmax) + expf(v3 - vmax);
    }
    for (int off = 16; off; off >>= 1)
        se += __shfl_down_sync(0xffffffffu, se, off);

    if (lane == 0) {
        float sig_obj = 1.f / (1.f + expf(-obj[warp]));
        float score   = sig_obj * (1.f / se);
        g_pack[warp] = make_float2(score, __int_as_float(amax));

        if (score >= CONF) {
            int slot = atomicAdd(&g_ccnt[amax], 1);
            if (slot < CAP)
                g_clist[amax * CAP + slot] = make_float2(score, __int_as_float(warp));
        }

        float s  = strd[warp];
        float gx = grid[warp * 2 + 0], gy = grid[warp * 2 + 1];
        float aw = anch[warp * 2 + 0], ah = anch[warp * 2 + 1];
        float4 r = ((const float4*)reg)[warp];

        float cx = (1.f / (1.f + expf(-r.x)) + gx) * s;
        float cy = (1.f / (1.f + expf(-r.y)) + gy) * s;
        float w  = expf(r.z) * aw;
        float h  = expf(r.w) * ah;

        float4 b;
        b.x = fminf(fmaxf((cx - 0.5f * w) / 640.0f, 0.f), 1.f);
        b.y = fminf(fmaxf((cy - 0.5f * h) / 640.0f, 0.f), 1.f);
        b.z = fminf(fmaxf((cx + 0.5f * w) / 640.0f, 0.f), 1.f);
        b.w = fminf(fmaxf((cy + 0.5f * h) / 640.0f, 0.f), 1.f);
        g_boxes4[warp] = b;
    }
}

// ---------------- kernel 2: per-class sort + fill + gather ----------------
__global__ void __launch_bounds__(BS) sortfill_kernel(
    float* __restrict__ out_boxes, int N)
{
    __shared__ float sc[CAP];
    __shared__ int   sidx[CAP];
    __shared__ int   s_run, s_wsum[BS / 32];

    const int cls  = blockIdx.x;
    const int tid  = threadIdx.x;
    const int wid  = tid >> 5;
    const int lane = tid & 31;

    if (tid == 0) s_run = 0;

    int cnt = min(g_ccnt[cls], CAP);

    // ---- Phase B: sort (score desc, idx asc) ----
    if (cnt <= BS) {
        // register+shuffle bitonic over fixed 512 elements
        float v = -FLT_MAX; int x = 0x7fffffff;
        if (tid < cnt) {
            float2 p = g_clist[cls * CAP + tid];
            v = p.x; x = __float_as_int(p.y);
        }
        #pragma unroll
        for (int k = 2; k <= BS; k <<= 1) {
            #pragma unroll
            for (int j = k >> 1; j > 0; j >>= 1) {
                float ov; int ox;
                if (j < 32) {
                    ov = __shfl_xor_sync(0xffffffffu, v, j);
                    ox = __shfl_xor_sync(0xffffffffu, x, j);
                } else {
                    __syncthreads();
                    sc[tid] = v; sidx[tid] = x;
                    __syncthreads();
                    ov = sc[tid ^ j]; ox = sidx[tid ^ j];
                }
                bool dir   = ((tid & k) == 0);
                bool isLow = ((tid & j) == 0);
                float lv = isLow ? v : ov;  int lx = isLow ? x : ox;
                float hv = isLow ? ov : v;  int hx = isLow ? ox : x;
                bool P = (lv > hv) || (lv == hv && lx < hx);  // low precedes high
                if (P != dir) { v = ov; x = ox; }
            }
        }
        __syncthreads();
        sc[tid] = v; sidx[tid] = x;
        // pad region beyond 512 unused (cnt <= 512, V <= cnt)
        __syncthreads();
    } else {
        // generic smem bitonic (cnt > 512)
        for (int q = tid; q < cnt; q += BS) {
            float2 p = g_clist[cls * CAP + q];
            sc[q]   = p.x;
            sidx[q] = __float_as_int(p.y);
        }
        int M = 2; while (M < cnt) M <<= 1;
        for (int i = cnt + tid; i < M; i += BS) { sc[i] = -FLT_MAX; sidx[i] = 0x7fffffff; }
        __syncthreads();
        for (int k = 2; k <= M; k <<= 1) {
            for (int j = k >> 1; j > 0; j >>= 1) {
                for (int i = tid; i < M; i += BS) {
                    int l = i ^ j;
                    if (l > i) {
                        float si = sc[i], sl = sc[l];
                        int   ii = sidx[i], il = sidx[l];
                        bool lPrec = (sl > si) || (sl == si && il < ii);
                        if (lPrec == ((i & k) == 0)) {
                            sc[i] = sl; sc[l] = si;
                            sidx[i] = il; sidx[l] = ii;
                        }
                    }
                }
                __syncthreads();
            }
        }
    }

    // ---- Phase C: fill remaining slots with lowest-index non-candidates ----
    const int V = min(cnt, KTOP);
    const int need = KTOP - V;
    if (need > 0) {
        for (int base = 0;; base += BS) {
            int a = base + tid;
            int flag = 0;
            if (a < N) {
                float2 p = g_pack[a];
                flag = !(__float_as_int(p.y) == cls && p.x >= CONF);
            }
            unsigned m = __ballot_sync(0xffffffffu, flag);
            int wpos = __popc(m & ((1u << lane) - 1u));
            if (lane == 0) s_wsum[wid] = __popc(m);
            __syncthreads();
            int off = 0, tot = 0;
            #pragma unroll
            for (int w = 0; w < BS / 32; w++) {
                if (w < wid) off += s_wsum[w];
                tot += s_wsum[w];
            }
            int run = s_run;
            int pos = run + off + wpos;
            if (flag && pos < need && V + pos < CAP) { sc[V + pos] = -1.0f; sidx[V + pos] = a; }
            __syncthreads();
            if (tid == 0) s_run = run + tot;
            __syncthreads();
            if (run + tot >= need) break;
            if (base + BS >= N) break;
        }
    }
    __syncthreads();

    if (tid == 0) { g_V[cls] = V; g_ccnt[cls] = 0; }  // reset for next replay

    // ---- Phase D: gather boxes -> out_boxes; stage first V; export ----
    const bool fast = (V <= VMAXF);
    for (int k = tid; k < KTOP; k += BS) {
        int a = sidx[k];
        float4 b = g_boxes4[a];
        if (fast && k < V) {
            g_sbox[cls * VMAXF + k] = b;
            g_sarA[cls * VMAXF + k] = (b.z - b.x) * (b.w - b.y);
        }
        ((float4*)out_boxes)[(size_t)cls * KTOP + k] = b;
        g_ssc[cls * KTOP + k]  = sc[k];
        g_sidx[cls * KTOP + k] = sidx[k];
    }
}

// ---------------- kernel 3: tiled IoU mask build (grid C x MSPLIT) ----------------
__global__ void __launch_bounds__(BS) mask_kernel()
{
    __shared__ float bx1[VMAXF], by1[VMAXF], bx2[VMAXF], by2[VMAXF], sar[VMAXF];

    const int cls  = blockIdx.x;
    const int tid  = threadIdx.x;
    const int wid  = tid >> 5;
    const int lane = tid & 31;

    const int V = g_V[cls];
    if (V > VMAXF) return;

    for (int k = tid; k < V; k += BS) {
        float4 b = g_sbox[cls * VMAXF + k];
        bx1[k] = b.x; by1[k] = b.y; bx2[k] = b.z; by2[k] = b.w;
        sar[k] = g_sarA[cls * VMAXF + k];
    }
    __syncthreads();

    const int nt = (V + 31) >> 5;
    const int T  = nt * (nt + 1) / 2;
    unsigned* maskC = g_mask + (size_t)cls * VMAXF * MW;
    unsigned* flagC = g_flag + cls * 16;

    for (int t = blockIdx.y + MSPLIT * wid; t < T; t += MSPLIT * (BS / 32)) {
        int ti = 0, rem = t;
        while (rem >= nt - ti) { rem -= nt - ti; ti++; }
        int tj = ti + rem;

        int j = (tj << 5) + lane;
        bool vj = j < V;
        float xj1 = 0.f, yj1 = 0.f, xj2 = 0.f, yj2 = 0.f, aj = 0.f;
        if (vj) { xj1 = bx1[j]; yj1 = by1[j]; xj2 = bx2[j]; yj2 = by2[j]; aj = sar[j]; }

        int imax = min(32, V - (ti << 5));
        for (int r = 0; r < imax; r++) {
            int i = (ti << 5) + r;
            float xi1 = bx1[i], yi1 = by1[i], xi2 = bx2[i], yi2 = by2[i];
            float ai  = sar[i];
            float xx1 = fmaxf(xi1, xj1);
            float yy1 = fmaxf(yi1, yj1);
            float xx2 = fminf(xi2, xj2);
            float yy2 = fminf(yi2, yj2);
            float ww = fmaxf(1e-28f, xx2 - xx1);
            float hh = fmaxf(1e-28f, yy2 - yy1);
            float inter = ww * hh;
            float iou = inter / (ai + aj - inter + 1e-14f);
            bool bit = vj && (j > i) && (iou > NMS_THR);
            unsigned word = __ballot_sync(0xffffffffu, bit);
            if (lane == 0) {
                maskC[i * MW + tj] = word;      // every upper-tri word written once
                if (word) atomicOr(&flagC[i >> 5], 1u << (i & 31));
            }
        }
    }
}

// ---------------- kernel 4: resolve + outputs ----------------
__global__ void __launch_bounds__(256) resolve_out_kernel(
    float* __restrict__ out_scores, float* __restrict__ out_keep)
{
    __shared__ unsigned smask[VMAXF * MW];
    __shared__ unsigned s_flag[16];
    __shared__ unsigned aliveW[16];

    const int cls = blockIdx.x;
    const int tid = threadIdx.x;
    const int V   = g_V[cls];

    if (V <= VMAXF) {
        if (tid < 16) s_flag[tid] = g_flag[cls * 16 + tid];
        const unsigned* maskC = g_mask + (size_t)cls * VMAXF * MW;
        for (int p = tid; p < V * MW; p += 256) smask[p] = maskC[p];
        __syncthreads();

        // single thread, alive bitset in registers
        if (tid == 0) {
            unsigned alive[MW], flg[MW];
            #pragma unroll
            for (int w = 0; w < MW; w++) {
                int lo = w << 5;
                unsigned a = 0;
                if (lo + 32 <= V)      a = 0xffffffffu;
                else if (lo < V)       a = (1u << (V - lo)) - 1u;
                alive[w] = a;
                flg[w]   = s_flag[w];
            }
            #pragma unroll
            for (int w0 = 0; w0 < MW; w0++) {
                if ((w0 << 5) >= V) break;
                unsigned done = 0;
                while (true) {
                    unsigned aw = alive[w0] & ~done;
                    if (!aw) break;
                    unsigned actw = aw & flg[w0];
                    if (!actw) break;              // rest of word suppresses nothing
                    int b = __ffs(actw) - 1;
                    int i = (w0 << 5) + b;
                    done |= (aw & ((1u << b) - 1u)) | (1u << b);
                    const unsigned* row = &smask[i * MW];
                    #pragma unroll
                    for (int w = 0; w < MW; w++)
                        if (w >= w0) alive[w] &= ~row[w];   // compile-time guard (lower-tri unwritten)
                }
            }
            #pragma unroll
            for (int w = 0; w < MW; w++) aliveW[w] = alive[w];
            for (int w = MW; w < 16; w++) aliveW[w] = 0u;
        }
        __syncthreads();

        for (int k = tid; k < KTOP; k += 256) {
            float kp = 0.f;
            if (k < V) kp = ((aliveW[k >> 5] >> (k & 31)) & 1u) ? 1.f : 0.f;
            out_scores[(size_t)cls * KTOP + k] = g_ssc[cls * KTOP + k] * kp;
            out_keep[(size_t)cls * KTOP + k]   = kp;
        }
        __syncthreads();
        if (tid < 16) g_flag[cls * 16 + tid] = 0u;   // reset for next replay
    } else {
        // fallback: barriered greedy NMS from global data
        int* kfb = (int*)smask;
        for (int k = tid; k < V; k += 256) kfb[k] = 1;
        __syncthreads();
        for (int i = 0; i < V; i++) {
            if (kfb[i]) {
                float4 bi = g_boxes4[g_sidx[cls * KTOP + i]];
                float ai = (bi.z - bi.x) * (bi.w - bi.y);
                for (int j = i + 1 + tid; j < V; j += 256) {
                    if (kfb[j]) {
                        float4 bj = g_boxes4[g_sidx[cls * KTOP + j]];
                        float aj = (bj.z - bj.x) * (bj.w - bj.y);
                        float xx1 = fmaxf(bi.x, bj.x);
                        float yy1 = fmaxf(bi.y, bj.y);
                        float xx2 = fminf(bi.z, bj.z);
                        float yy2 = fminf(bi.w, bj.w);
                        float ww = fmaxf(1e-28f, xx2 - xx1);
                        float hh = fmaxf(1e-28f, yy2 - yy1);
                        float inter = ww * hh;
                        float iou = inter / (ai + aj - inter + 1e-14f);
                        if (iou > NMS_THR) kfb[j] = 0;
                    }
                }
            }
            __syncthreads();
        }
        for (int k = tid; k < KTOP; k += 256) {
            float kp = (k < V && kfb[k]) ? 1.f : 0.f;
            out_scores[(size_t)cls * KTOP + k] = g_ssc[cls * KTOP + k] * kp;
            out_keep[(size_t)cls * KTOP + k]   = kp;
        }
        __syncthreads();
        if (tid < 16) g_flag[cls * 16 + tid] = 0u;
    }
}

// ---------------- launch ----------------
extern "C" void kernel_launch(void* const* d_in, const int* in_sizes, int n_in,
                              void* d_out, int out_size)
{
    const float* reg  = (const float*)d_in[0];
    const float* obj  = (const float*)d_in[1];
    const float* cls  = (const float*)d_in[2];
    const float* grid = (const float*)d_in[3];
    const float* anch = (const float*)d_in[4];
    const float* strd = (const float*)d_in[5];

    int N = in_sizes[0] / 4;
    int C = in_sizes[2] / N;

    float* out = (float*)d_out;
    float* out_boxes  = out;                         // [C, K, 4]
    float* out_scores = out + (size_t)C * KTOP * 4;  // [C, K]
    float* out_keep   = out + (size_t)C * KTOP * 5;  // [C, K]

    int blocks = (N + 7) / 8;
    decode_kernel<<<blocks, 256>>>(reg, obj, cls, grid, anch, strd, N, C);
    sortfill_kernel<<<C, BS>>>(out_boxes, N);
    mask_kernel<<<dim3(C, MSPLIT), BS>>>();
    resolve_out_kernel<<<C, 256>>>(out_scores, out_keep);
}